// round 11
// baseline (speedup 1.0000x reference)
#include <cuda_runtime.h>
#include <cuda_fp16.h>
#include <cstdint>

#define N_NODES 50000
#define N_EDGES 800000
#define E_TOT   (N_EDGES + N_NODES)
#define D 128
#define H 4
#define NB ((N_NODES + 1023) / 1024)       // 49 scan blocks (1024 nodes each)
#define GGRID ((N_NODES + 127) / 128)      // 391 gemm blocks
#define CNT_BLK ((N_EDGES + 255) / 256)    // 3125 count blocks
#define EP_BLK ((E_TOT + 255) / 256)       // 3321 edge-weight blocks
#define LOG2E 1.4426950408889634f

// ---------------- scratch (static device globals; no allocs) ----------------
__device__ __align__(16) float  g_h  [N_NODES * D];
__device__ __align__(16) float  g_h2 [N_NODES * D];
__device__ __align__(16) __half g_xph[N_NODES * D];   // fp16 messages
__device__ __align__(16) float  g_als[N_NODES * H];   // pre-scaled by LOG2E
__device__ __align__(16) float  g_ald[N_NODES * H];   // pre-scaled by LOG2E
__device__ __align__(16) float  g_p  [E_TOT * H];     // per-edge softmax weights
__device__ int g_deg[N_NODES];    // zero-init; count fills, scan1 zeroes,
                                  // scatter uses as cursor, agg re-zeroes
__device__ int g_rowptr[N_NODES + 1];   // block-LOCAL exclusive offsets
__device__ int g_col[E_TOT];            // src node per edge slot
__device__ int g_dst[E_TOT];            // dst node per edge slot
__device__ int g_bsum[64];
__device__ int g_sbex[64];              // global exclusive block offsets
__device__ int g_gemm_done;             // spin-fence counters (self-resetting)
__device__ int g_ep_done;

// ---------------- tf32 GEMM body (device fn; fat-kernel friendly) ----------------
__device__ __forceinline__ uint32_t f2tf32(float f) {
    uint32_t r;
    asm("cvt.rna.tf32.f32 %0, %1;" : "=r"(r) : "f"(f));
    return r;
}

__device__ void gemm_body(
        const float* Aext, int asel,
        const float* __restrict__ W,
        const float* __restrict__ bias,
        int csel,
        const float* __restrict__ asrc,
        const float* __restrict__ adst,
        int bidx) {
    __shared__ uint32_t As[128 * 36];   // [m][k], stride 36
    __shared__ uint32_t Bs[32 * 136];   // [k][n], stride 136

    const float* A = Aext ? Aext : (asel == 0 ? g_h : g_h2);
    float* Cp = (csel == 0 ? g_h : g_h2);

    const int bm = bidx * 128;
    const int tid = threadIdx.x;
    const int wid = tid >> 5, lane = tid & 31;
    const int g = lane >> 2, tig = lane & 3;
    const int wm = (wid & 3) * 32;
    const int wn = (wid >> 2) * 64;

    float acc[2][8][4];
#pragma unroll
    for (int mt = 0; mt < 2; mt++)
#pragma unroll
        for (int nt = 0; nt < 8; nt++)
#pragma unroll
            for (int q = 0; q < 4; q++) acc[mt][nt][q] = 0.f;

    for (int k0 = 0; k0 < 128; k0 += 32) {
#pragma unroll
        for (int it = 0; it < 4; it++) {
            int idx = tid + 256 * it;
            int row = idx >> 3, c4 = (idx & 7) << 2;
            float4 v = make_float4(0.f, 0.f, 0.f, 0.f);
            if (bm + row < N_NODES)
                v = *(const float4*)(A + (size_t)(bm + row) * D + k0 + c4);
            uint32_t* p = &As[row * 36 + c4];
            p[0] = f2tf32(v.x); p[1] = f2tf32(v.y);
            p[2] = f2tf32(v.z); p[3] = f2tf32(v.w);
        }
#pragma unroll
        for (int it = 0; it < 4; it++) {
            int idx = tid + 256 * it;
            int row = idx >> 5, c4 = (idx & 31) << 2;
            float4 v = *(const float4*)(W + (size_t)(k0 + row) * D + c4);
            uint32_t* p = &Bs[row * 136 + c4];
            p[0] = f2tf32(v.x); p[1] = f2tf32(v.y);
            p[2] = f2tf32(v.z); p[3] = f2tf32(v.w);
        }
        __syncthreads();

#pragma unroll
        for (int kk = 0; kk < 32; kk += 8) {
            uint32_t a[2][4], b[8][2];
#pragma unroll
            for (int mt = 0; mt < 2; mt++) {
                int r0 = wm + mt * 16 + g;
                a[mt][0] = As[r0 * 36 + kk + tig];
                a[mt][1] = As[(r0 + 8) * 36 + kk + tig];
                a[mt][2] = As[r0 * 36 + kk + tig + 4];
                a[mt][3] = As[(r0 + 8) * 36 + kk + tig + 4];
            }
#pragma unroll
            for (int nt = 0; nt < 8; nt++) {
                int c0 = wn + nt * 8 + g;
                b[nt][0] = Bs[(kk + tig) * 136 + c0];
                b[nt][1] = Bs[(kk + tig + 4) * 136 + c0];
            }
#pragma unroll
            for (int mt = 0; mt < 2; mt++)
#pragma unroll
                for (int nt = 0; nt < 8; nt++) {
                    asm volatile(
                        "mma.sync.aligned.m16n8k8.row.col.f32.tf32.tf32.f32 "
                        "{%0,%1,%2,%3}, {%4,%5,%6,%7}, {%8,%9}, {%0,%1,%2,%3};"
                        : "+f"(acc[mt][nt][0]), "+f"(acc[mt][nt][1]),
                          "+f"(acc[mt][nt][2]), "+f"(acc[mt][nt][3])
                        : "r"(a[mt][0]), "r"(a[mt][1]),
                          "r"(a[mt][2]), "r"(a[mt][3]),
                          "r"(b[nt][0]), "r"(b[nt][1]));
                }
        }
        __syncthreads();
    }

    if (asrc == nullptr) {
#pragma unroll
        for (int mt = 0; mt < 2; mt++) {
            int row = bm + wm + mt * 16 + g;
#pragma unroll
            for (int nt = 0; nt < 8; nt++) {
                int col = wn + nt * 8 + 2 * tig;
                float bx = bias ? bias[col] : 0.f;
                float by = bias ? bias[col + 1] : 0.f;
                if (row < N_NODES)
                    *(float2*)(Cp + (size_t)row * D + col) =
                        make_float2(acc[mt][nt][0] + bx, acc[mt][nt][1] + by);
                if (row + 8 < N_NODES)
                    *(float2*)(Cp + (size_t)(row + 8) * D + col) =
                        make_float2(acc[mt][nt][2] + bx, acc[mt][nt][3] + by);
            }
        }
    } else {
        // xp epilogue: fp16 message store + fused logits (pre-scaled by LOG2E)
        const int head_base = (wn == 0) ? 0 : 2;
#pragma unroll
        for (int mt = 0; mt < 2; mt++) {
#pragma unroll
            for (int rh = 0; rh < 2; rh++) {
                int row = bm + wm + mt * 16 + rh * 8 + g;
                float ps0 = 0.f, ps1 = 0.f, pd0 = 0.f, pd1 = 0.f;
#pragma unroll
                for (int nt = 0; nt < 8; nt++) {
                    int col = wn + nt * 8 + 2 * tig;
                    int c = (nt & 3) * 8 + 2 * tig;
                    int hl = nt >> 2;
                    float v0 = acc[mt][nt][rh * 2 + 0];
                    float v1 = acc[mt][nt][rh * 2 + 1];
                    float s0 = __ldg(asrc + (head_base + hl) * 32 + c);
                    float s1 = __ldg(asrc + (head_base + hl) * 32 + c + 1);
                    float d0 = __ldg(adst + (head_base + hl) * 32 + c);
                    float d1 = __ldg(adst + (head_base + hl) * 32 + c + 1);
                    if (hl == 0) { ps0 += v0 * s0 + v1 * s1; pd0 += v0 * d0 + v1 * d1; }
                    else         { ps1 += v0 * s0 + v1 * s1; pd1 += v0 * d0 + v1 * d1; }
                    if (row < N_NODES)
                        *(__half2*)(g_xph + (size_t)row * D + col) =
                            __floats2half2_rn(v0, v1);
                }
#pragma unroll
                for (int off = 1; off < 4; off <<= 1) {
                    ps0 += __shfl_xor_sync(0xffffffffu, ps0, off);
                    ps1 += __shfl_xor_sync(0xffffffffu, ps1, off);
                    pd0 += __shfl_xor_sync(0xffffffffu, pd0, off);
                    pd1 += __shfl_xor_sync(0xffffffffu, pd1, off);
                }
                if (tig == 0 && row < N_NODES) {
                    g_als[row * 4 + head_base]     = ps0 * LOG2E;
                    g_als[row * 4 + head_base + 1] = ps1 * LOG2E;
                    g_ald[row * 4 + head_base]     = pd0 * LOG2E;
                    g_ald[row * 4 + head_base + 1] = pd1 * LOG2E;
                }
            }
        }
    }
}

// ---------------- scan1 body: 256-thr block scans 1024 nodes ----------------
__device__ void scan1_body(int b) {
    __shared__ int sm[256];
    int t = threadIdx.x;
    int base = b * 1024 + t * 4;
    int v0 = 0, v1 = 0, v2 = 0, v3 = 0;
    if (base + 3 < N_NODES) {
        int4 d = *(int4*)&g_deg[base];
        v0 = d.x + 1; v1 = d.y + 1; v2 = d.z + 1; v3 = d.w + 1;
        *(int4*)&g_deg[base] = make_int4(0, 0, 0, 0);
    } else {
        if (base + 0 < N_NODES) { v0 = g_deg[base + 0] + 1; g_deg[base + 0] = 0; }
        if (base + 1 < N_NODES) { v1 = g_deg[base + 1] + 1; g_deg[base + 1] = 0; }
        if (base + 2 < N_NODES) { v2 = g_deg[base + 2] + 1; g_deg[base + 2] = 0; }
        if (base + 3 < N_NODES) { v3 = g_deg[base + 3] + 1; g_deg[base + 3] = 0; }
    }
    int s = v0 + v1 + v2 + v3;
    sm[t] = s;
    __syncthreads();
#pragma unroll
    for (int off = 1; off < 256; off <<= 1) {
        int x = (t >= off) ? sm[t - off] : 0;
        __syncthreads();
        sm[t] += x;
        __syncthreads();
    }
    int run = sm[t] - s;
    if (base + 0 < N_NODES) g_rowptr[base + 0] = run; run += v0;
    if (base + 1 < N_NODES) g_rowptr[base + 1] = run; run += v1;
    if (base + 2 < N_NODES) g_rowptr[base + 2] = run; run += v2;
    if (base + 3 < N_NODES) g_rowptr[base + 3] = run;
    if (t == 255) g_bsum[b] = sm[255];
}

// ---------------- per-edge softmax weight (4 heads) ----------------
__device__ __forceinline__ float4 edge_p(int s, int d) {
    float4 as4 = *(const float4*)&g_als[(size_t)s * 4];
    float4 ad4 = *(const float4*)&g_ald[(size_t)d * 4];
    float e0 = as4.x + ad4.x; e0 = fmaxf(e0, 0.2f * e0);
    float e1 = as4.y + ad4.y; e1 = fmaxf(e1, 0.2f * e1);
    float e2 = as4.z + ad4.z; e2 = fmaxf(e2, 0.2f * e2);
    float e3 = as4.w + ad4.w; e3 = fmaxf(e3, 0.2f * e3);
    return make_float4(exp2f(e0), exp2f(e1), exp2f(e2), exp2f(e3));
}

// ---------------- fat kernels: GEMM ∥ CSR stage ----------------
__global__ void __launch_bounds__(256) k_fused0(
        const float* x, const float* __restrict__ w0,
        const float* __restrict__ b0, const int* __restrict__ ei) {
    if (blockIdx.x < GGRID) {
        gemm_body(x, 0, w0, b0, 0, nullptr, nullptr, blockIdx.x);
    } else {
        int i = (blockIdx.x - GGRID) * 256 + threadIdx.x;
        if (i < N_EDGES) atomicAdd(&g_deg[ei[N_EDGES + i]], 1);
    }
}

__global__ void __launch_bounds__(256) k_fused1(
        const float* __restrict__ W,
        const float* __restrict__ asrc, const float* __restrict__ adst) {
    if (blockIdx.x < GGRID) {
        gemm_body(nullptr, 0, W, nullptr, 0, asrc, adst, blockIdx.x);
    } else {
        scan1_body(blockIdx.x - GGRID);
    }
}

// ---------------- fused GEMM + edge-weight kernel (spin-fence) --------------
// Blocks [0, GGRID): gemm for this layer, then signal.
// Blocks [GGRID, GGRID+EP_BLK): wait for all gemm blocks (forward progress is
// guaranteed: gemm blocks are dispatched first, never wait, and fit in the
// resident set), then compute per-edge softmax weights from fresh als/ald.
// Last edge block resets the counters so the graph replay starts clean.
__global__ void __launch_bounds__(256) k_gemm_ep(
        int asel, const float* __restrict__ W,
        const float* __restrict__ asrc, const float* __restrict__ adst) {
    if (blockIdx.x < GGRID) {
        gemm_body(nullptr, asel, W, nullptr, 0, asrc, adst, blockIdx.x);
        __threadfence();
        __syncthreads();
        if (threadIdx.x == 0) atomicAdd(&g_gemm_done, 1);
    } else {
        if (threadIdx.x == 0) {
            while (*(volatile int*)&g_gemm_done < GGRID) __nanosleep(100);
        }
        __syncthreads();
        __threadfence();
        int e = (blockIdx.x - GGRID) * 256 + threadIdx.x;
        if (e < E_TOT) {
            int s = g_col[e];
            int d = g_dst[e];
            *(float4*)&g_p[(size_t)e * 4] = edge_p(s, d);
        }
        __threadfence();
        __syncthreads();
        if (threadIdx.x == 0) {
            int c = atomicAdd(&g_ep_done, 1);
            if (c == EP_BLK - 1) {          // last edge block: reset for replay
                g_gemm_done = 0;
                g_ep_done = 0;
            }
        }
    }
}

// ---------------- scatter: build col/dst AND layer-1 edge weights ------------
__global__ void __launch_bounds__(256) k_scatter(const int* __restrict__ ei) {
    __shared__ int sb[64];
    __shared__ int sb_ex[64];
    int t = threadIdx.x;
    if (t < 64) sb[t] = (t < NB) ? g_bsum[t] : 0;
    __syncthreads();
#pragma unroll
    for (int off = 1; off < 64; off <<= 1) {
        int x = (t < 64 && t >= off) ? sb[t - off] : 0;
        __syncthreads();
        if (t < 64) sb[t] += x;
        __syncthreads();
    }
    if (t < 64) sb_ex[t] = (t == 0) ? 0 : sb[t - 1];
    __syncthreads();
    if (blockIdx.x == 0 && t < 64) g_sbex[t] = sb_ex[t];   // publish for aggs

    int i = blockIdx.x * blockDim.x + t;
    int s, d;
    if (i < N_NODES) {
        s = i; d = i;                                       // self loop
    } else if (i < N_NODES + N_EDGES) {
        int j = i - N_NODES;
        s = ei[j]; d = ei[N_EDGES + j];
    } else return;
    int c = atomicAdd(&g_deg[d], 1);
    int pos = g_rowptr[d] + sb_ex[d >> 10] + c;
    g_col[pos] = s;
    g_dst[pos] = d;
    *(float4*)&g_p[(size_t)pos * 4] = edge_p(s, d);        // layer-1 weights
}

// ---------------- softmax-aggregate: ONE warp per destination node ----------
// p precomputed; loop = col LDG + p LDG + fp16 xp LDG + cvt + FMA.
__global__ void __launch_bounds__(256) k_agg(
        int in_sel, float* out_ext, int out_sel,
        const float* __restrict__ bias, int relu_res) {
    int n = (blockIdx.x * blockDim.x + threadIdx.x) >> 5;
    if (n >= N_NODES) return;
    int lane = threadIdx.x & 31;
    const float* xin = (in_sel == 0) ? g_h : g_h2;
    float* outp = out_ext ? out_ext : (out_sel == 0 ? g_h : g_h2);
    int hh = lane >> 3;

    int beg = __ldg(&g_rowptr[n]) + __ldg(&g_sbex[n >> 10]);
    int end = (n == N_NODES - 1) ? E_TOT
              : (__ldg(&g_rowptr[n + 1]) + __ldg(&g_sbex[(n + 1) >> 10]));

    float4 acc = make_float4(0.f, 0.f, 0.f, 0.f);
    float ssum = 0.f;

    int j = beg;
    for (; j + 4 <= end; j += 4) {
        int s0 = __ldg(&g_col[j]);
        int s1 = __ldg(&g_col[j + 1]);
        int s2 = __ldg(&g_col[j + 2]);
        int s3 = __ldg(&g_col[j + 3]);
        float p0 = __ldg(&g_p[(size_t)j * 4 + hh]);
        float p1 = __ldg(&g_p[(size_t)j * 4 + 4 + hh]);
        float p2 = __ldg(&g_p[(size_t)j * 4 + 8 + hh]);
        float p3 = __ldg(&g_p[(size_t)j * 4 + 12 + hh]);
        uint2 u0 = *(const uint2*)(g_xph + (size_t)s0 * D + lane * 4);
        uint2 u1 = *(const uint2*)(g_xph + (size_t)s1 * D + lane * 4);
        uint2 u2 = *(const uint2*)(g_xph + (size_t)s2 * D + lane * 4);
        uint2 u3 = *(const uint2*)(g_xph + (size_t)s3 * D + lane * 4);
        ssum += p0 + p1 + p2 + p3;
        float2 f00 = __half22float2(*(__half2*)&u0.x);
        float2 f01 = __half22float2(*(__half2*)&u0.y);
        float2 f10 = __half22float2(*(__half2*)&u1.x);
        float2 f11 = __half22float2(*(__half2*)&u1.y);
        float2 f20 = __half22float2(*(__half2*)&u2.x);
        float2 f21 = __half22float2(*(__half2*)&u2.y);
        float2 f30 = __half22float2(*(__half2*)&u3.x);
        float2 f31 = __half22float2(*(__half2*)&u3.y);
        acc.x += p0 * f00.x; acc.y += p0 * f00.y;
        acc.z += p0 * f01.x; acc.w += p0 * f01.y;
        acc.x += p1 * f10.x; acc.y += p1 * f10.y;
        acc.z += p1 * f11.x; acc.w += p1 * f11.y;
        acc.x += p2 * f20.x; acc.y += p2 * f20.y;
        acc.z += p2 * f21.x; acc.w += p2 * f21.y;
        acc.x += p3 * f30.x; acc.y += p3 * f30.y;
        acc.z += p3 * f31.x; acc.w += p3 * f31.y;
    }
    for (; j < end; j++) {
        int s0 = __ldg(&g_col[j]);
        float p0 = __ldg(&g_p[(size_t)j * 4 + hh]);
        uint2 u0 = *(const uint2*)(g_xph + (size_t)s0 * D + lane * 4);
        ssum += p0;
        float2 f00 = __half22float2(*(__half2*)&u0.x);
        float2 f01 = __half22float2(*(__half2*)&u0.y);
        acc.x += p0 * f00.x; acc.y += p0 * f00.y;
        acc.z += p0 * f01.x; acc.w += p0 * f01.y;
    }

    float inv = 1.f / ssum;
    float4 bv = *(const float4*)(bias + lane * 4);
    float4 o;
    o.x = acc.x * inv + bv.x;
    o.y = acc.y * inv + bv.y;
    o.z = acc.z * inv + bv.z;
    o.w = acc.w * inv + bv.w;
    if (relu_res) {
        float4 r = *(const float4*)(xin + (size_t)n * D + lane * 4);
        o.x = fmaxf(o.x + r.x, 0.f);
        o.y = fmaxf(o.y + r.y, 0.f);
        o.z = fmaxf(o.z + r.z, 0.f);
        o.w = fmaxf(o.w + r.w, 0.f);
    }
    *(float4*)(outp + (size_t)n * D + lane * 4) = o;
    if (lane == 0) g_deg[n] = 0;       // reset cursor for next replay
}

// ---------------- launch (8 kernels) ----------------
extern "C" void kernel_launch(void* const* d_in, const int* in_sizes, int n_in,
                              void* d_out, int out_size) {
    const float* x   = (const float*)d_in[0];
    const int*   ei  = (const int*)  d_in[1];
    const float* w0  = (const float*)d_in[2];
    const float* b0  = (const float*)d_in[3];
    const float* w1  = (const float*)d_in[4];
    const float* as1 = (const float*)d_in[5];
    const float* ad1 = (const float*)d_in[6];
    const float* b1  = (const float*)d_in[7];
    const float* w2  = (const float*)d_in[8];
    const float* as2 = (const float*)d_in[9];
    const float* ad2 = (const float*)d_in[10];
    const float* b2  = (const float*)d_in[11];
    const float* w3  = (const float*)d_in[12];
    const float* as3 = (const float*)d_in[13];
    const float* ad3 = (const float*)d_in[14];
    const float* b3  = (const float*)d_in[15];
    float* out = (float*)d_out;

    int agrid = (N_NODES * 32) / 256;       // 6250 blocks, 1 warp per node
    int egrid = (E_TOT + 255) / 256;        // 3321 blocks

    // L0: gemm0 (x@w0+b0 -> g_h)  ∥  edge-count histogram
    k_fused0<<<GGRID + CNT_BLK, 256>>>(x, w0, b0, ei);
    // L1: gemm1 (g_h@w1 -> xph/als/ald)  ∥  scan1
    k_fused1<<<GGRID + NB, 256>>>(w1, as1, ad1);
    // CSR finalize + layer-1 edge weights
    k_scatter<<<egrid, 256>>>(ei);
    // layer 1 aggregate: g_h residual -> g_h2
    k_agg<<<agrid, 256>>>(0, nullptr, 1, b1, 1);
    // layer 2: gemm + edge weights in ONE launch (spin-fence)
    k_gemm_ep<<<GGRID + EP_BLK, 256>>>(1, w2, as2, ad2);
    k_agg<<<agrid, 256>>>(1, nullptr, 0, b2, 1);
    // layer 3: gemm + edge weights in ONE launch (spin-fence)
    k_gemm_ep<<<GGRID + EP_BLK, 256>>>(0, w3, as3, ad3);
    k_agg<<<agrid, 256>>>(0, out, 0, b3, 0);
}

// round 12
// speedup vs baseline: 1.1673x; 1.1673x over previous
#include <cuda_runtime.h>
#include <cuda_fp16.h>
#include <cstdint>

#define N_NODES 50000
#define N_EDGES 800000
#define E_TOT   (N_EDGES + N_NODES)
#define D 128
#define H 4
#define NB ((N_NODES + 1023) / 1024)       // 49 scan blocks (1024 nodes each)
#define GGRID ((N_NODES + 127) / 128)      // 391 gemm blocks
#define CNT_BLK ((N_EDGES + 255) / 256)    // 3125 count blocks
#define LOG2E 1.4426950408889634f

// ---------------- scratch (static device globals; no allocs) ----------------
__device__ __align__(16) float  g_h  [N_NODES * D];
__device__ __align__(16) float  g_h2 [N_NODES * D];
__device__ __align__(16) __half g_xph[N_NODES * D];   // fp16 messages
__device__ __align__(16) float  g_als[N_NODES * H];   // pre-scaled by LOG2E
__device__ __align__(16) float  g_ald[N_NODES * H];   // pre-scaled by LOG2E
__device__ __align__(16) float  g_p  [H * E_TOT];     // HEAD-PLANE layout [h][e]
__device__ int g_deg[N_NODES];    // zero-init; count fills, scan1 zeroes,
                                  // scatter uses as cursor, agg re-zeroes
__device__ int g_rowptr[N_NODES + 1];   // block-LOCAL exclusive offsets
__device__ __align__(16) int g_col[E_TOT];   // src node per edge slot
__device__ int g_dst[E_TOT];                 // dst node per edge slot
__device__ int g_bsum[64];
__device__ int g_sbex[64];              // global exclusive block offsets

// ---------------- tf32 GEMM body (device fn; fat-kernel friendly) ----------------
__device__ __forceinline__ uint32_t f2tf32(float f) {
    uint32_t r;
    asm("cvt.rna.tf32.f32 %0, %1;" : "=r"(r) : "f"(f));
    return r;
}

__device__ void gemm_body(
        const float* Aext, int asel,
        const float* __restrict__ W,
        const float* __restrict__ bias,
        int csel,
        const float* __restrict__ asrc,
        const float* __restrict__ adst,
        int bidx) {
    __shared__ uint32_t As[128 * 36];   // [m][k], stride 36
    __shared__ uint32_t Bs[32 * 136];   // [k][n], stride 136

    const float* A = Aext ? Aext : (asel == 0 ? g_h : g_h2);
    float* Cp = (csel == 0 ? g_h : g_h2);

    const int bm = bidx * 128;
    const int tid = threadIdx.x;
    const int wid = tid >> 5, lane = tid & 31;
    const int g = lane >> 2, tig = lane & 3;
    const int wm = (wid & 3) * 32;
    const int wn = (wid >> 2) * 64;

    float acc[2][8][4];
#pragma unroll
    for (int mt = 0; mt < 2; mt++)
#pragma unroll
        for (int nt = 0; nt < 8; nt++)
#pragma unroll
            for (int q = 0; q < 4; q++) acc[mt][nt][q] = 0.f;

    for (int k0 = 0; k0 < 128; k0 += 32) {
#pragma unroll
        for (int it = 0; it < 4; it++) {
            int idx = tid + 256 * it;
            int row = idx >> 3, c4 = (idx & 7) << 2;
            float4 v = make_float4(0.f, 0.f, 0.f, 0.f);
            if (bm + row < N_NODES)
                v = *(const float4*)(A + (size_t)(bm + row) * D + k0 + c4);
            uint32_t* p = &As[row * 36 + c4];
            p[0] = f2tf32(v.x); p[1] = f2tf32(v.y);
            p[2] = f2tf32(v.z); p[3] = f2tf32(v.w);
        }
#pragma unroll
        for (int it = 0; it < 4; it++) {
            int idx = tid + 256 * it;
            int row = idx >> 5, c4 = (idx & 31) << 2;
            float4 v = *(const float4*)(W + (size_t)(k0 + row) * D + c4);
            uint32_t* p = &Bs[row * 136 + c4];
            p[0] = f2tf32(v.x); p[1] = f2tf32(v.y);
            p[2] = f2tf32(v.z); p[3] = f2tf32(v.w);
        }
        __syncthreads();

#pragma unroll
        for (int kk = 0; kk < 32; kk += 8) {
            uint32_t a[2][4], b[8][2];
#pragma unroll
            for (int mt = 0; mt < 2; mt++) {
                int r0 = wm + mt * 16 + g;
                a[mt][0] = As[r0 * 36 + kk + tig];
                a[mt][1] = As[(r0 + 8) * 36 + kk + tig];
                a[mt][2] = As[r0 * 36 + kk + tig + 4];
                a[mt][3] = As[(r0 + 8) * 36 + kk + tig + 4];
            }
#pragma unroll
            for (int nt = 0; nt < 8; nt++) {
                int c0 = wn + nt * 8 + g;
                b[nt][0] = Bs[(kk + tig) * 136 + c0];
                b[nt][1] = Bs[(kk + tig + 4) * 136 + c0];
            }
#pragma unroll
            for (int mt = 0; mt < 2; mt++)
#pragma unroll
                for (int nt = 0; nt < 8; nt++) {
                    asm volatile(
                        "mma.sync.aligned.m16n8k8.row.col.f32.tf32.tf32.f32 "
                        "{%0,%1,%2,%3}, {%4,%5,%6,%7}, {%8,%9}, {%0,%1,%2,%3};"
                        : "+f"(acc[mt][nt][0]), "+f"(acc[mt][nt][1]),
                          "+f"(acc[mt][nt][2]), "+f"(acc[mt][nt][3])
                        : "r"(a[mt][0]), "r"(a[mt][1]),
                          "r"(a[mt][2]), "r"(a[mt][3]),
                          "r"(b[nt][0]), "r"(b[nt][1]));
                }
        }
        __syncthreads();
    }

    if (asrc == nullptr) {
#pragma unroll
        for (int mt = 0; mt < 2; mt++) {
            int row = bm + wm + mt * 16 + g;
#pragma unroll
            for (int nt = 0; nt < 8; nt++) {
                int col = wn + nt * 8 + 2 * tig;
                float bx = bias ? bias[col] : 0.f;
                float by = bias ? bias[col + 1] : 0.f;
                if (row < N_NODES)
                    *(float2*)(Cp + (size_t)row * D + col) =
                        make_float2(acc[mt][nt][0] + bx, acc[mt][nt][1] + by);
                if (row + 8 < N_NODES)
                    *(float2*)(Cp + (size_t)(row + 8) * D + col) =
                        make_float2(acc[mt][nt][2] + bx, acc[mt][nt][3] + by);
            }
        }
    } else {
        // xp epilogue: fp16 message store + fused logits (pre-scaled by LOG2E)
        const int head_base = (wn == 0) ? 0 : 2;
#pragma unroll
        for (int mt = 0; mt < 2; mt++) {
#pragma unroll
            for (int rh = 0; rh < 2; rh++) {
                int row = bm + wm + mt * 16 + rh * 8 + g;
                float ps0 = 0.f, ps1 = 0.f, pd0 = 0.f, pd1 = 0.f;
#pragma unroll
                for (int nt = 0; nt < 8; nt++) {
                    int col = wn + nt * 8 + 2 * tig;
                    int c = (nt & 3) * 8 + 2 * tig;
                    int hl = nt >> 2;
                    float v0 = acc[mt][nt][rh * 2 + 0];
                    float v1 = acc[mt][nt][rh * 2 + 1];
                    float s0 = __ldg(asrc + (head_base + hl) * 32 + c);
                    float s1 = __ldg(asrc + (head_base + hl) * 32 + c + 1);
                    float d0 = __ldg(adst + (head_base + hl) * 32 + c);
                    float d1 = __ldg(adst + (head_base + hl) * 32 + c + 1);
                    if (hl == 0) { ps0 += v0 * s0 + v1 * s1; pd0 += v0 * d0 + v1 * d1; }
                    else         { ps1 += v0 * s0 + v1 * s1; pd1 += v0 * d0 + v1 * d1; }
                    if (row < N_NODES)
                        *(__half2*)(g_xph + (size_t)row * D + col) =
                            __floats2half2_rn(v0, v1);
                }
#pragma unroll
                for (int off = 1; off < 4; off <<= 1) {
                    ps0 += __shfl_xor_sync(0xffffffffu, ps0, off);
                    ps1 += __shfl_xor_sync(0xffffffffu, ps1, off);
                    pd0 += __shfl_xor_sync(0xffffffffu, pd0, off);
                    pd1 += __shfl_xor_sync(0xffffffffu, pd1, off);
                }
                if (tig == 0 && row < N_NODES) {
                    g_als[row * 4 + head_base]     = ps0 * LOG2E;
                    g_als[row * 4 + head_base + 1] = ps1 * LOG2E;
                    g_ald[row * 4 + head_base]     = pd0 * LOG2E;
                    g_ald[row * 4 + head_base + 1] = pd1 * LOG2E;
                }
            }
        }
    }
}

// ---------------- scan1 body: 256-thr block scans 1024 nodes ----------------
__device__ void scan1_body(int b) {
    __shared__ int sm[256];
    int t = threadIdx.x;
    int base = b * 1024 + t * 4;
    int v0 = 0, v1 = 0, v2 = 0, v3 = 0;
    if (base + 3 < N_NODES) {
        int4 d = *(int4*)&g_deg[base];
        v0 = d.x + 1; v1 = d.y + 1; v2 = d.z + 1; v3 = d.w + 1;
        *(int4*)&g_deg[base] = make_int4(0, 0, 0, 0);
    } else {
        if (base + 0 < N_NODES) { v0 = g_deg[base + 0] + 1; g_deg[base + 0] = 0; }
        if (base + 1 < N_NODES) { v1 = g_deg[base + 1] + 1; g_deg[base + 1] = 0; }
        if (base + 2 < N_NODES) { v2 = g_deg[base + 2] + 1; g_deg[base + 2] = 0; }
        if (base + 3 < N_NODES) { v3 = g_deg[base + 3] + 1; g_deg[base + 3] = 0; }
    }
    int s = v0 + v1 + v2 + v3;
    sm[t] = s;
    __syncthreads();
#pragma unroll
    for (int off = 1; off < 256; off <<= 1) {
        int x = (t >= off) ? sm[t - off] : 0;
        __syncthreads();
        sm[t] += x;
        __syncthreads();
    }
    int run = sm[t] - s;
    if (base + 0 < N_NODES) g_rowptr[base + 0] = run; run += v0;
    if (base + 1 < N_NODES) g_rowptr[base + 1] = run; run += v1;
    if (base + 2 < N_NODES) g_rowptr[base + 2] = run; run += v2;
    if (base + 3 < N_NODES) g_rowptr[base + 3] = run;
    if (t == 255) g_bsum[b] = sm[255];
}

// ---------------- per-edge softmax weight (4 heads) ----------------
__device__ __forceinline__ float4 edge_p(int s, int d) {
    float4 as4 = *(const float4*)&g_als[(size_t)s * 4];
    float4 ad4 = *(const float4*)&g_ald[(size_t)d * 4];
    float e0 = as4.x + ad4.x; e0 = fmaxf(e0, 0.2f * e0);
    float e1 = as4.y + ad4.y; e1 = fmaxf(e1, 0.2f * e1);
    float e2 = as4.z + ad4.z; e2 = fmaxf(e2, 0.2f * e2);
    float e3 = as4.w + ad4.w; e3 = fmaxf(e3, 0.2f * e3);
    return make_float4(exp2f(e0), exp2f(e1), exp2f(e2), exp2f(e3));
}

// ---------------- fat kernels: GEMM ∥ CSR stage ----------------
__global__ void __launch_bounds__(256) k_fused0(
        const float* x, const float* __restrict__ w0,
        const float* __restrict__ b0, const int* __restrict__ ei) {
    if (blockIdx.x < GGRID) {
        gemm_body(x, 0, w0, b0, 0, nullptr, nullptr, blockIdx.x);
    } else {
        int i = (blockIdx.x - GGRID) * 256 + threadIdx.x;
        if (i < N_EDGES) atomicAdd(&g_deg[ei[N_EDGES + i]], 1);
    }
}

__global__ void __launch_bounds__(256) k_fused1(
        const float* __restrict__ W,
        const float* __restrict__ asrc, const float* __restrict__ adst) {
    if (blockIdx.x < GGRID) {
        gemm_body(nullptr, 0, W, nullptr, 0, asrc, adst, blockIdx.x);
    } else {
        scan1_body(blockIdx.x - GGRID);
    }
}

__global__ void __launch_bounds__(256) k_gemm_tc(
        const float* Aext, int asel,
        const float* __restrict__ W,
        const float* __restrict__ bias,
        int csel,
        const float* __restrict__ asrc,
        const float* __restrict__ adst) {
    gemm_body(Aext, asel, W, bias, csel, asrc, adst, blockIdx.x);
}

// ---------------- scatter: build col/dst AND layer-1 edge weights ------------
__global__ void __launch_bounds__(256) k_scatter(const int* __restrict__ ei) {
    __shared__ int sb[64];
    __shared__ int sb_ex[64];
    int t = threadIdx.x;
    if (t < 64) sb[t] = (t < NB) ? g_bsum[t] : 0;
    __syncthreads();
#pragma unroll
    for (int off = 1; off < 64; off <<= 1) {
        int x = (t < 64 && t >= off) ? sb[t - off] : 0;
        __syncthreads();
        if (t < 64) sb[t] += x;
        __syncthreads();
    }
    if (t < 64) sb_ex[t] = (t == 0) ? 0 : sb[t - 1];
    __syncthreads();
    if (blockIdx.x == 0 && t < 64) g_sbex[t] = sb_ex[t];   // publish for aggs

    int i = blockIdx.x * blockDim.x + t;
    int s, d;
    if (i < N_NODES) {
        s = i; d = i;                                       // self loop
    } else if (i < N_NODES + N_EDGES) {
        int j = i - N_NODES;
        s = ei[j]; d = ei[N_EDGES + j];
    } else return;
    int c = atomicAdd(&g_deg[d], 1);
    int pos = g_rowptr[d] + sb_ex[d >> 10] + c;
    g_col[pos] = s;
    g_dst[pos] = d;
    float4 p = edge_p(s, d);                               // layer-1 weights
    g_p[0 * E_TOT + pos] = p.x;
    g_p[1 * E_TOT + pos] = p.y;
    g_p[2 * E_TOT + pos] = p.z;
    g_p[3 * E_TOT + pos] = p.w;
}

// ---------------- edge weights for layers 2/3 (head-plane layout) ------------
__global__ void __launch_bounds__(256) k_edgep() {
    int e = blockIdx.x * blockDim.x + threadIdx.x;
    if (e >= E_TOT) return;
    int s = __ldg(&g_col[e]);
    int d = __ldg(&g_dst[e]);
    float4 p = edge_p(s, d);
    g_p[0 * E_TOT + e] = p.x;
    g_p[1 * E_TOT + e] = p.y;
    g_p[2 * E_TOT + e] = p.z;
    g_p[3 * E_TOT + e] = p.w;
}

// ---------------- softmax-aggregate: ONE warp per destination node ----------
// Vectorized streams: per 4 edges, ONE int4 col load + ONE float4 p load
// (head-plane) + 4 fp16 xph gathers. Scalar peel/tail for 16B alignment.
__global__ void __launch_bounds__(256) k_agg(
        int in_sel, float* out_ext, int out_sel,
        const float* __restrict__ bias, int relu_res) {
    int n = (blockIdx.x * blockDim.x + threadIdx.x) >> 5;
    if (n >= N_NODES) return;
    int lane = threadIdx.x & 31;
    const float* xin = (in_sel == 0) ? g_h : g_h2;
    float* outp = out_ext ? out_ext : (out_sel == 0 ? g_h : g_h2);
    int hh = lane >> 3;
    const float* pp = g_p + (size_t)hh * E_TOT;   // this lane's head plane

    int beg = __ldg(&g_rowptr[n]) + __ldg(&g_sbex[n >> 10]);
    int end = (n == N_NODES - 1) ? E_TOT
              : (__ldg(&g_rowptr[n + 1]) + __ldg(&g_sbex[(n + 1) >> 10]));

    float4 acc = make_float4(0.f, 0.f, 0.f, 0.f);
    float ssum = 0.f;
    int j = beg;

    // scalar peel to 4-edge alignment
    for (; j < end && (j & 3); j++) {
        int s0 = __ldg(&g_col[j]);
        float p0 = __ldg(&pp[j]);
        uint2 u0 = *(const uint2*)(g_xph + (size_t)s0 * D + lane * 4);
        ssum += p0;
        float2 f00 = __half22float2(*(__half2*)&u0.x);
        float2 f01 = __half22float2(*(__half2*)&u0.y);
        acc.x += p0 * f00.x; acc.y += p0 * f00.y;
        acc.z += p0 * f01.x; acc.w += p0 * f01.y;
    }
    // vectorized main loop
    for (; j + 4 <= end; j += 4) {
        int4  sv = __ldg((const int4*)&g_col[j]);     // 4 srcs, one LDG.128
        float4 pv = __ldg((const float4*)&pp[j]);     // 4 weights, one LDG.128
        uint2 u0 = *(const uint2*)(g_xph + (size_t)sv.x * D + lane * 4);
        uint2 u1 = *(const uint2*)(g_xph + (size_t)sv.y * D + lane * 4);
        uint2 u2 = *(const uint2*)(g_xph + (size_t)sv.z * D + lane * 4);
        uint2 u3 = *(const uint2*)(g_xph + (size_t)sv.w * D + lane * 4);
        ssum += pv.x + pv.y + pv.z + pv.w;
        float2 f00 = __half22float2(*(__half2*)&u0.x);
        float2 f01 = __half22float2(*(__half2*)&u0.y);
        float2 f10 = __half22float2(*(__half2*)&u1.x);
        float2 f11 = __half22float2(*(__half2*)&u1.y);
        float2 f20 = __half22float2(*(__half2*)&u2.x);
        float2 f21 = __half22float2(*(__half2*)&u2.y);
        float2 f30 = __half22float2(*(__half2*)&u3.x);
        float2 f31 = __half22float2(*(__half2*)&u3.y);
        acc.x += pv.x * f00.x; acc.y += pv.x * f00.y;
        acc.z += pv.x * f01.x; acc.w += pv.x * f01.y;
        acc.x += pv.y * f10.x; acc.y += pv.y * f10.y;
        acc.z += pv.y * f11.x; acc.w += pv.y * f11.y;
        acc.x += pv.z * f20.x; acc.y += pv.z * f20.y;
        acc.z += pv.z * f21.x; acc.w += pv.z * f21.y;
        acc.x += pv.w * f30.x; acc.y += pv.w * f30.y;
        acc.z += pv.w * f31.x; acc.w += pv.w * f31.y;
    }
    // scalar tail
    for (; j < end; j++) {
        int s0 = __ldg(&g_col[j]);
        float p0 = __ldg(&pp[j]);
        uint2 u0 = *(const uint2*)(g_xph + (size_t)s0 * D + lane * 4);
        ssum += p0;
        float2 f00 = __half22float2(*(__half2*)&u0.x);
        float2 f01 = __half22float2(*(__half2*)&u0.y);
        acc.x += p0 * f00.x; acc.y += p0 * f00.y;
        acc.z += p0 * f01.x; acc.w += p0 * f01.y;
    }

    float inv = 1.f / ssum;
    float4 bv = *(const float4*)(bias + lane * 4);
    float4 o;
    o.x = acc.x * inv + bv.x;
    o.y = acc.y * inv + bv.y;
    o.z = acc.z * inv + bv.z;
    o.w = acc.w * inv + bv.w;
    if (relu_res) {
        float4 r = *(const float4*)(xin + (size_t)n * D + lane * 4);
        o.x = fmaxf(o.x + r.x, 0.f);
        o.y = fmaxf(o.y + r.y, 0.f);
        o.z = fmaxf(o.z + r.z, 0.f);
        o.w = fmaxf(o.w + r.w, 0.f);
    }
    *(float4*)(outp + (size_t)n * D + lane * 4) = o;
    if (lane == 0) g_deg[n] = 0;       // reset cursor for next replay
}

// ---------------- launch (10 kernels) ----------------
extern "C" void kernel_launch(void* const* d_in, const int* in_sizes, int n_in,
                              void* d_out, int out_size) {
    const float* x   = (const float*)d_in[0];
    const int*   ei  = (const int*)  d_in[1];
    const float* w0  = (const float*)d_in[2];
    const float* b0  = (const float*)d_in[3];
    const float* w1  = (const float*)d_in[4];
    const float* as1 = (const float*)d_in[5];
    const float* ad1 = (const float*)d_in[6];
    const float* b1  = (const float*)d_in[7];
    const float* w2  = (const float*)d_in[8];
    const float* as2 = (const float*)d_in[9];
    const float* ad2 = (const float*)d_in[10];
    const float* b2  = (const float*)d_in[11];
    const float* w3  = (const float*)d_in[12];
    const float* as3 = (const float*)d_in[13];
    const float* ad3 = (const float*)d_in[14];
    const float* b3  = (const float*)d_in[15];
    float* out = (float*)d_out;

    int agrid = (N_NODES * 32) / 256;       // 6250 blocks, 1 warp per node
    int egrid = (E_TOT + 255) / 256;        // 3321 blocks

    // L0: gemm0 (x@w0+b0 -> g_h)  ∥  edge-count histogram
    k_fused0<<<GGRID + CNT_BLK, 256>>>(x, w0, b0, ei);
    // L1: gemm1 (g_h@w1 -> xph/als/ald)  ∥  scan1
    k_fused1<<<GGRID + NB, 256>>>(w1, as1, ad1);
    // CSR finalize + layer-1 edge weights
    k_scatter<<<egrid, 256>>>(ei);
    // layer 1 aggregate: g_h residual -> g_h2
    k_agg<<<agrid, 256>>>(0, nullptr, 1, b1, 1);
    // layer 2
    k_gemm_tc<<<GGRID, 256>>>(nullptr, 1, w2, nullptr, 0, as2, ad2);
    k_edgep<<<egrid, 256>>>();
    k_agg<<<agrid, 256>>>(1, nullptr, 0, b2, 1);
    // layer 3
    k_gemm_tc<<<GGRID, 256>>>(nullptr, 0, w3, nullptr, 0, as3, ad3);
    k_edgep<<<egrid, 256>>>();
    k_agg<<<agrid, 256>>>(0, out, 0, b3, 0);
}

// round 13
// speedup vs baseline: 1.2402x; 1.0624x over previous
#include <cuda_runtime.h>
#include <cuda_fp16.h>
#include <cstdint>

#define N_NODES 50000
#define N_EDGES 800000
#define E_TOT   (N_EDGES + N_NODES)
#define D 128
#define H 4
#define NB ((N_NODES + 1023) / 1024)       // 49 scan blocks (1024 nodes each)
#define GGRID ((N_NODES + 127) / 128)      // 391 gemm blocks
#define CNT_BLK ((N_EDGES + 255) / 256)    // 3125 count blocks
#define SCT_BLK ((E_TOT + 255) / 256)      // 3321 scatter blocks
#define LOG2E 1.4426950408889634f

// ---------------- scratch (static device globals; no allocs) ----------------
__device__ __align__(16) float  g_h  [N_NODES * D];
__device__ __align__(16) float  g_h2 [N_NODES * D];
__device__ __align__(16) __half g_xph[N_NODES * D];   // fp16 messages
__device__ __align__(16) float  g_als[N_NODES * H];   // pre-scaled by LOG2E
__device__ __align__(16) float  g_ald[N_NODES * H];   // pre-scaled by LOG2E
__device__ int g_deg[N_NODES];    // zero-init; count fills, scan1 zeroes,
                                  // scatter uses as cursor, agg re-zeroes
__device__ int g_rowptr[N_NODES + 1];   // block-LOCAL exclusive offsets
__device__ int g_col[E_TOT];            // src node per edge slot
__device__ int g_bsum[64];
__device__ int g_sbex[64];              // global exclusive block offsets

// ---------------- tf32 GEMM body (device fn; fat-kernel friendly) ----------------
__device__ __forceinline__ uint32_t f2tf32(float f) {
    uint32_t r;
    asm("cvt.rna.tf32.f32 %0, %1;" : "=r"(r) : "f"(f));
    return r;
}

__device__ void gemm_body(
        const float* Aext, int asel,
        const float* __restrict__ W,
        const float* __restrict__ bias,
        int csel,
        const float* __restrict__ asrc,
        const float* __restrict__ adst,
        int bidx) {
    __shared__ uint32_t As[128 * 36];   // [m][k], stride 36
    __shared__ uint32_t Bs[32 * 136];   // [k][n], stride 136

    const float* A = Aext ? Aext : (asel == 0 ? g_h : g_h2);
    float* Cp = (csel == 0 ? g_h : g_h2);

    const int bm = bidx * 128;
    const int tid = threadIdx.x;
    const int wid = tid >> 5, lane = tid & 31;
    const int g = lane >> 2, tig = lane & 3;
    const int wm = (wid & 3) * 32;
    const int wn = (wid >> 2) * 64;

    float acc[2][8][4];
#pragma unroll
    for (int mt = 0; mt < 2; mt++)
#pragma unroll
        for (int nt = 0; nt < 8; nt++)
#pragma unroll
            for (int q = 0; q < 4; q++) acc[mt][nt][q] = 0.f;

    for (int k0 = 0; k0 < 128; k0 += 32) {
#pragma unroll
        for (int it = 0; it < 4; it++) {
            int idx = tid + 256 * it;
            int row = idx >> 3, c4 = (idx & 7) << 2;
            float4 v = make_float4(0.f, 0.f, 0.f, 0.f);
            if (bm + row < N_NODES)
                v = *(const float4*)(A + (size_t)(bm + row) * D + k0 + c4);
            uint32_t* p = &As[row * 36 + c4];
            p[0] = f2tf32(v.x); p[1] = f2tf32(v.y);
            p[2] = f2tf32(v.z); p[3] = f2tf32(v.w);
        }
#pragma unroll
        for (int it = 0; it < 4; it++) {
            int idx = tid + 256 * it;
            int row = idx >> 5, c4 = (idx & 31) << 2;
            float4 v = *(const float4*)(W + (size_t)(k0 + row) * D + c4);
            uint32_t* p = &Bs[row * 136 + c4];
            p[0] = f2tf32(v.x); p[1] = f2tf32(v.y);
            p[2] = f2tf32(v.z); p[3] = f2tf32(v.w);
        }
        __syncthreads();

#pragma unroll
        for (int kk = 0; kk < 32; kk += 8) {
            uint32_t a[2][4], b[8][2];
#pragma unroll
            for (int mt = 0; mt < 2; mt++) {
                int r0 = wm + mt * 16 + g;
                a[mt][0] = As[r0 * 36 + kk + tig];
                a[mt][1] = As[(r0 + 8) * 36 + kk + tig];
                a[mt][2] = As[r0 * 36 + kk + tig + 4];
                a[mt][3] = As[(r0 + 8) * 36 + kk + tig + 4];
            }
#pragma unroll
            for (int nt = 0; nt < 8; nt++) {
                int c0 = wn + nt * 8 + g;
                b[nt][0] = Bs[(kk + tig) * 136 + c0];
                b[nt][1] = Bs[(kk + tig + 4) * 136 + c0];
            }
#pragma unroll
            for (int mt = 0; mt < 2; mt++)
#pragma unroll
                for (int nt = 0; nt < 8; nt++) {
                    asm volatile(
                        "mma.sync.aligned.m16n8k8.row.col.f32.tf32.tf32.f32 "
                        "{%0,%1,%2,%3}, {%4,%5,%6,%7}, {%8,%9}, {%0,%1,%2,%3};"
                        : "+f"(acc[mt][nt][0]), "+f"(acc[mt][nt][1]),
                          "+f"(acc[mt][nt][2]), "+f"(acc[mt][nt][3])
                        : "r"(a[mt][0]), "r"(a[mt][1]),
                          "r"(a[mt][2]), "r"(a[mt][3]),
                          "r"(b[nt][0]), "r"(b[nt][1]));
                }
        }
        __syncthreads();
    }

    if (asrc == nullptr) {
#pragma unroll
        for (int mt = 0; mt < 2; mt++) {
            int row = bm + wm + mt * 16 + g;
#pragma unroll
            for (int nt = 0; nt < 8; nt++) {
                int col = wn + nt * 8 + 2 * tig;
                float bx = bias ? bias[col] : 0.f;
                float by = bias ? bias[col + 1] : 0.f;
                if (row < N_NODES)
                    *(float2*)(Cp + (size_t)row * D + col) =
                        make_float2(acc[mt][nt][0] + bx, acc[mt][nt][1] + by);
                if (row + 8 < N_NODES)
                    *(float2*)(Cp + (size_t)(row + 8) * D + col) =
                        make_float2(acc[mt][nt][2] + bx, acc[mt][nt][3] + by);
            }
        }
    } else {
        // xp epilogue: fp16 message store + fused logits (pre-scaled by LOG2E)
        const int head_base = (wn == 0) ? 0 : 2;
#pragma unroll
        for (int mt = 0; mt < 2; mt++) {
#pragma unroll
            for (int rh = 0; rh < 2; rh++) {
                int row = bm + wm + mt * 16 + rh * 8 + g;
                float ps0 = 0.f, ps1 = 0.f, pd0 = 0.f, pd1 = 0.f;
#pragma unroll
                for (int nt = 0; nt < 8; nt++) {
                    int col = wn + nt * 8 + 2 * tig;
                    int c = (nt & 3) * 8 + 2 * tig;
                    int hl = nt >> 2;
                    float v0 = acc[mt][nt][rh * 2 + 0];
                    float v1 = acc[mt][nt][rh * 2 + 1];
                    float s0 = __ldg(asrc + (head_base + hl) * 32 + c);
                    float s1 = __ldg(asrc + (head_base + hl) * 32 + c + 1);
                    float d0 = __ldg(adst + (head_base + hl) * 32 + c);
                    float d1 = __ldg(adst + (head_base + hl) * 32 + c + 1);
                    if (hl == 0) { ps0 += v0 * s0 + v1 * s1; pd0 += v0 * d0 + v1 * d1; }
                    else         { ps1 += v0 * s0 + v1 * s1; pd1 += v0 * d0 + v1 * d1; }
                    if (row < N_NODES)
                        *(__half2*)(g_xph + (size_t)row * D + col) =
                            __floats2half2_rn(v0, v1);
                }
#pragma unroll
                for (int off = 1; off < 4; off <<= 1) {
                    ps0 += __shfl_xor_sync(0xffffffffu, ps0, off);
                    ps1 += __shfl_xor_sync(0xffffffffu, ps1, off);
                    pd0 += __shfl_xor_sync(0xffffffffu, pd0, off);
                    pd1 += __shfl_xor_sync(0xffffffffu, pd1, off);
                }
                if (tig == 0 && row < N_NODES) {
                    g_als[row * 4 + head_base]     = ps0 * LOG2E;
                    g_als[row * 4 + head_base + 1] = ps1 * LOG2E;
                    g_ald[row * 4 + head_base]     = pd0 * LOG2E;
                    g_ald[row * 4 + head_base + 1] = pd1 * LOG2E;
                }
            }
        }
    }
}

// ---------------- scan1: 256-thr block scans 1024 nodes ----------------
// exclusive scan of (deg+1); consumes & re-zeroes deg; bsum[b] = block total.
__global__ void __launch_bounds__(256) k_scan1() {
    __shared__ int sm[256];
    int b = blockIdx.x;
    int t = threadIdx.x;
    int base = b * 1024 + t * 4;
    int v0 = 0, v1 = 0, v2 = 0, v3 = 0;
    if (base + 3 < N_NODES) {
        int4 d = *(int4*)&g_deg[base];
        v0 = d.x + 1; v1 = d.y + 1; v2 = d.z + 1; v3 = d.w + 1;
        *(int4*)&g_deg[base] = make_int4(0, 0, 0, 0);
    } else {
        if (base + 0 < N_NODES) { v0 = g_deg[base + 0] + 1; g_deg[base + 0] = 0; }
        if (base + 1 < N_NODES) { v1 = g_deg[base + 1] + 1; g_deg[base + 1] = 0; }
        if (base + 2 < N_NODES) { v2 = g_deg[base + 2] + 1; g_deg[base + 2] = 0; }
        if (base + 3 < N_NODES) { v3 = g_deg[base + 3] + 1; g_deg[base + 3] = 0; }
    }
    int s = v0 + v1 + v2 + v3;
    sm[t] = s;
    __syncthreads();
#pragma unroll
    for (int off = 1; off < 256; off <<= 1) {
        int x = (t >= off) ? sm[t - off] : 0;
        __syncthreads();
        sm[t] += x;
        __syncthreads();
    }
    int run = sm[t] - s;                       // exclusive within block
    if (base + 0 < N_NODES) g_rowptr[base + 0] = run; run += v0;
    if (base + 1 < N_NODES) g_rowptr[base + 1] = run; run += v1;
    if (base + 2 < N_NODES) g_rowptr[base + 2] = run; run += v2;
    if (base + 3 < N_NODES) g_rowptr[base + 3] = run;
    if (t == 255) g_bsum[b] = sm[255];
}

// ---------------- scatter body (depends ONLY on scan1, not on any GEMM) -----
__device__ void scatter_body(int b, const int* __restrict__ ei) {
    __shared__ int sb[64];
    __shared__ int sb_ex[64];
    int t = threadIdx.x;
    if (t < 64) sb[t] = (t < NB) ? g_bsum[t] : 0;
    __syncthreads();
#pragma unroll
    for (int off = 1; off < 64; off <<= 1) {
        int x = (t < 64 && t >= off) ? sb[t - off] : 0;
        __syncthreads();
        if (t < 64) sb[t] += x;
        __syncthreads();
    }
    if (t < 64) sb_ex[t] = (t == 0) ? 0 : sb[t - 1];
    __syncthreads();
    if (b == 0 && t < 64) g_sbex[t] = sb_ex[t];   // publish for aggs

    int i = b * 256 + t;
    if (i < N_NODES) {
        int c = atomicAdd(&g_deg[i], 1);
        g_col[g_rowptr[i] + sb_ex[i >> 10] + c] = i;       // self loop
    } else if (i < N_NODES + N_EDGES) {
        int j = i - N_NODES;
        int s = ei[j], d = ei[N_EDGES + j];
        int c = atomicAdd(&g_deg[d], 1);
        g_col[g_rowptr[d] + sb_ex[d >> 10] + c] = s;
    }
}

// ---------------- fat kernels ----------------
// L0: gemm0 (x@w0+b0 -> g_h) ∥ edge-count histogram
__global__ void __launch_bounds__(256) k_fused0(
        const float* x, const float* __restrict__ w0,
        const float* __restrict__ b0, const int* __restrict__ ei) {
    if (blockIdx.x < GGRID) {
        gemm_body(x, 0, w0, b0, 0, nullptr, nullptr, blockIdx.x);
    } else {
        int i = (blockIdx.x - GGRID) * 256 + threadIdx.x;
        if (i < N_EDGES) atomicAdd(&g_deg[ei[N_EDGES + i]], 1);
    }
}

// L2: gemm1 (g_h@w1 -> xph/als/ald) ∥ scatter — INDEPENDENT block ranges,
// no waiting anywhere (scatter needs only scan1 from the previous launch).
__global__ void __launch_bounds__(256) k_fused_g1sc(
        const float* __restrict__ W,
        const float* __restrict__ asrc, const float* __restrict__ adst,
        const int* __restrict__ ei) {
    if (blockIdx.x < GGRID) {
        gemm_body(nullptr, 0, W, nullptr, 0, asrc, adst, blockIdx.x);
    } else {
        scatter_body(blockIdx.x - GGRID, ei);
    }
}

// plain GEMM launcher for layers 2/3
__global__ void __launch_bounds__(256) k_gemm_tc(
        const float* Aext, int asel,
        const float* __restrict__ W,
        const float* __restrict__ bias,
        int csel,
        const float* __restrict__ asrc,
        const float* __restrict__ adst) {
    gemm_body(Aext, asel, W, bias, csel, asrc, adst, blockIdx.x);
}

// ---------------- softmax-aggregate: ONE warp per destination node ----------
// Inline p: broadcast col LDG + per-lane als LDG + fp16 xph gather; logits
// pre-scaled by log2(e) so weight = EX2 only. 4-edge unroll for MLP depth.
__global__ void __launch_bounds__(256) k_agg(
        int in_sel, float* out_ext, int out_sel,
        const float* __restrict__ bias, int relu_res) {
    int n = (blockIdx.x * blockDim.x + threadIdx.x) >> 5;
    if (n >= N_NODES) return;
    int lane = threadIdx.x & 31;
    const float* xin = (in_sel == 0) ? g_h : g_h2;
    float* outp = out_ext ? out_ext : (out_sel == 0 ? g_h : g_h2);
    int hh = lane >> 3;
    float ad = g_ald[n * 4 + hh];

    int beg = __ldg(&g_rowptr[n]) + __ldg(&g_sbex[n >> 10]);
    int end = (n == N_NODES - 1) ? E_TOT
              : (__ldg(&g_rowptr[n + 1]) + __ldg(&g_sbex[(n + 1) >> 10]));

    float4 acc = make_float4(0.f, 0.f, 0.f, 0.f);
    float ssum = 0.f;

    int j = beg;
    for (; j + 4 <= end; j += 4) {
        int s0 = __ldg(&g_col[j]);
        int s1 = __ldg(&g_col[j + 1]);
        int s2 = __ldg(&g_col[j + 2]);
        int s3 = __ldg(&g_col[j + 3]);
        float a0 = __ldg(&g_als[(size_t)s0 * 4 + hh]);
        float a1 = __ldg(&g_als[(size_t)s1 * 4 + hh]);
        float a2 = __ldg(&g_als[(size_t)s2 * 4 + hh]);
        float a3 = __ldg(&g_als[(size_t)s3 * 4 + hh]);
        uint2 u0 = *(const uint2*)(g_xph + (size_t)s0 * D + lane * 4);
        uint2 u1 = *(const uint2*)(g_xph + (size_t)s1 * D + lane * 4);
        uint2 u2 = *(const uint2*)(g_xph + (size_t)s2 * D + lane * 4);
        uint2 u3 = *(const uint2*)(g_xph + (size_t)s3 * D + lane * 4);
        float e0 = a0 + ad; e0 = fmaxf(e0, 0.2f * e0);
        float e1 = a1 + ad; e1 = fmaxf(e1, 0.2f * e1);
        float e2 = a2 + ad; e2 = fmaxf(e2, 0.2f * e2);
        float e3 = a3 + ad; e3 = fmaxf(e3, 0.2f * e3);
        float p0 = exp2f(e0), p1 = exp2f(e1);
        float p2 = exp2f(e2), p3 = exp2f(e3);
        ssum += p0 + p1 + p2 + p3;
        float2 f00 = __half22float2(*(__half2*)&u0.x);
        float2 f01 = __half22float2(*(__half2*)&u0.y);
        float2 f10 = __half22float2(*(__half2*)&u1.x);
        float2 f11 = __half22float2(*(__half2*)&u1.y);
        float2 f20 = __half22float2(*(__half2*)&u2.x);
        float2 f21 = __half22float2(*(__half2*)&u2.y);
        float2 f30 = __half22float2(*(__half2*)&u3.x);
        float2 f31 = __half22float2(*(__half2*)&u3.y);
        acc.x += p0 * f00.x; acc.y += p0 * f00.y;
        acc.z += p0 * f01.x; acc.w += p0 * f01.y;
        acc.x += p1 * f10.x; acc.y += p1 * f10.y;
        acc.z += p1 * f11.x; acc.w += p1 * f11.y;
        acc.x += p2 * f20.x; acc.y += p2 * f20.y;
        acc.z += p2 * f21.x; acc.w += p2 * f21.y;
        acc.x += p3 * f30.x; acc.y += p3 * f30.y;
        acc.z += p3 * f31.x; acc.w += p3 * f31.y;
    }
    for (; j < end; j++) {
        int s0 = __ldg(&g_col[j]);
        float a0 = __ldg(&g_als[(size_t)s0 * 4 + hh]);
        uint2 u0 = *(const uint2*)(g_xph + (size_t)s0 * D + lane * 4);
        float e0 = a0 + ad; e0 = fmaxf(e0, 0.2f * e0);
        float p0 = exp2f(e0);
        ssum += p0;
        float2 f00 = __half22float2(*(__half2*)&u0.x);
        float2 f01 = __half22float2(*(__half2*)&u0.y);
        acc.x += p0 * f00.x; acc.y += p0 * f00.y;
        acc.z += p0 * f01.x; acc.w += p0 * f01.y;
    }

    float inv = 1.f / ssum;
    float4 bv = *(const float4*)(bias + lane * 4);
    float4 o;
    o.x = acc.x * inv + bv.x;
    o.y = acc.y * inv + bv.y;
    o.z = acc.z * inv + bv.z;
    o.w = acc.w * inv + bv.w;
    if (relu_res) {
        float4 r = *(const float4*)(xin + (size_t)n * D + lane * 4);
        o.x = fmaxf(o.x + r.x, 0.f);
        o.y = fmaxf(o.y + r.y, 0.f);
        o.z = fmaxf(o.z + r.z, 0.f);
        o.w = fmaxf(o.w + r.w, 0.f);
    }
    *(float4*)(outp + (size_t)n * D + lane * 4) = o;
    if (lane == 0) g_deg[n] = 0;       // reset cursor for next replay
}

// ---------------- launch (9 kernels) ----------------
extern "C" void kernel_launch(void* const* d_in, const int* in_sizes, int n_in,
                              void* d_out, int out_size) {
    const float* x   = (const float*)d_in[0];
    const int*   ei  = (const int*)  d_in[1];
    const float* w0  = (const float*)d_in[2];
    const float* b0  = (const float*)d_in[3];
    const float* w1  = (const float*)d_in[4];
    const float* as1 = (const float*)d_in[5];
    const float* ad1 = (const float*)d_in[6];
    const float* b1  = (const float*)d_in[7];
    const float* w2  = (const float*)d_in[8];
    const float* as2 = (const float*)d_in[9];
    const float* ad2 = (const float*)d_in[10];
    const float* b2  = (const float*)d_in[11];
    const float* w3  = (const float*)d_in[12];
    const float* as3 = (const float*)d_in[13];
    const float* ad3 = (const float*)d_in[14];
    const float* b3  = (const float*)d_in[15];
    float* out = (float*)d_out;

    int agrid = (N_NODES * 32) / 256;       // 6250 blocks, 1 warp per node

    // L0: gemm0 (x@w0+b0 -> g_h)  ∥  edge-count histogram
    k_fused0<<<GGRID + CNT_BLK, 256>>>(x, w0, b0, ei);
    // L1: scan1 (small; consumes count, zeroes deg)
    k_scan1<<<NB, 256>>>();
    // L2: gemm1 (g_h@w1 -> xph/als/ald)  ∥  scatter (independent of gemm1)
    k_fused_g1sc<<<GGRID + SCT_BLK, 256>>>(w1, as1, ad1, ei);
    // layer 1 aggregate: g_h residual -> g_h2
    k_agg<<<agrid, 256>>>(0, nullptr, 1, b1, 1);
    // layer 2
    k_gemm_tc<<<GGRID, 256>>>(nullptr, 1, w2, nullptr, 0, as2, ad2);
    k_agg<<<agrid, 256>>>(1, nullptr, 0, b2, 1);
    // layer 3
    k_gemm_tc<<<GGRID, 256>>>(nullptr, 0, w3, nullptr, 0, as3, ad3);
    k_agg<<<agrid, 256>>>(0, out, 0, b3, 0);
}

// round 14
// speedup vs baseline: 1.2757x; 1.0287x over previous
#include <cuda_runtime.h>
#include <cuda_fp16.h>
#include <cstdint>

#define N_NODES 50000
#define N_EDGES 800000
#define E_TOT   (N_EDGES + N_NODES)
#define D 128
#define H 4
#define NB ((N_NODES + 1023) / 1024)       // 49 scan blocks (1024 nodes each)
#define GGRID ((N_NODES + 127) / 128)      // 391 gemm blocks
#define CNT_BLK ((N_EDGES + 255) / 256)    // 3125 count blocks
#define SCT_BLK ((E_TOT + 255) / 256)      // 3321 scatter blocks
#define LOG2E 1.4426950408889634f

// ---------------- scratch (static device globals; no allocs) ----------------
__device__ __align__(16) float  g_h  [N_NODES * D];
__device__ __align__(16) float  g_h2 [N_NODES * D];
__device__ __align__(16) __half g_xph[N_NODES * D];   // fp16 messages
__device__ __align__(16) float  g_als[N_NODES * H];   // pre-scaled by LOG2E
__device__ __align__(16) float  g_ald[N_NODES * H];   // pre-scaled by LOG2E
__device__ int g_deg[N_NODES];    // zero-init; count fills, scan1 zeroes,
                                  // scatter uses as cursor, agg re-zeroes
__device__ int g_rowptr[N_NODES + 1];   // block-LOCAL exclusive offsets
__device__ int g_col[E_TOT];            // src node per edge slot
__device__ int g_bsum[64];
__device__ int g_sbex[64];              // global exclusive block offsets

// ---------------- tf32 GEMM body (device fn; fat-kernel friendly) ----------------
__device__ __forceinline__ uint32_t f2tf32(float f) {
    uint32_t r;
    asm("cvt.rna.tf32.f32 %0, %1;" : "=r"(r) : "f"(f));
    return r;
}

__device__ void gemm_body(
        const float* Aext, int asel,
        const float* __restrict__ W,
        const float* __restrict__ bias,
        int csel,
        const float* __restrict__ asrc,
        const float* __restrict__ adst,
        int bidx) {
    __shared__ uint32_t As[128 * 36];   // [m][k], stride 36
    __shared__ uint32_t Bs[32 * 136];   // [k][n], stride 136

    const float* A = Aext ? Aext : (asel == 0 ? g_h : g_h2);
    float* Cp = (csel == 0 ? g_h : g_h2);

    const int bm = bidx * 128;
    const int tid = threadIdx.x;
    const int wid = tid >> 5, lane = tid & 31;
    const int g = lane >> 2, tig = lane & 3;
    const int wm = (wid & 3) * 32;
    const int wn = (wid >> 2) * 64;

    float acc[2][8][4];
#pragma unroll
    for (int mt = 0; mt < 2; mt++)
#pragma unroll
        for (int nt = 0; nt < 8; nt++)
#pragma unroll
            for (int q = 0; q < 4; q++) acc[mt][nt][q] = 0.f;

    for (int k0 = 0; k0 < 128; k0 += 32) {
#pragma unroll
        for (int it = 0; it < 4; it++) {
            int idx = tid + 256 * it;
            int row = idx >> 3, c4 = (idx & 7) << 2;
            float4 v = make_float4(0.f, 0.f, 0.f, 0.f);
            if (bm + row < N_NODES)
                v = *(const float4*)(A + (size_t)(bm + row) * D + k0 + c4);
            uint32_t* p = &As[row * 36 + c4];
            p[0] = f2tf32(v.x); p[1] = f2tf32(v.y);
            p[2] = f2tf32(v.z); p[3] = f2tf32(v.w);
        }
#pragma unroll
        for (int it = 0; it < 4; it++) {
            int idx = tid + 256 * it;
            int row = idx >> 5, c4 = (idx & 31) << 2;
            float4 v = *(const float4*)(W + (size_t)(k0 + row) * D + c4);
            uint32_t* p = &Bs[row * 136 + c4];
            p[0] = f2tf32(v.x); p[1] = f2tf32(v.y);
            p[2] = f2tf32(v.z); p[3] = f2tf32(v.w);
        }
        __syncthreads();

#pragma unroll
        for (int kk = 0; kk < 32; kk += 8) {
            uint32_t a[2][4], b[8][2];
#pragma unroll
            for (int mt = 0; mt < 2; mt++) {
                int r0 = wm + mt * 16 + g;
                a[mt][0] = As[r0 * 36 + kk + tig];
                a[mt][1] = As[(r0 + 8) * 36 + kk + tig];
                a[mt][2] = As[r0 * 36 + kk + tig + 4];
                a[mt][3] = As[(r0 + 8) * 36 + kk + tig + 4];
            }
#pragma unroll
            for (int nt = 0; nt < 8; nt++) {
                int c0 = wn + nt * 8 + g;
                b[nt][0] = Bs[(kk + tig) * 136 + c0];
                b[nt][1] = Bs[(kk + tig + 4) * 136 + c0];
            }
#pragma unroll
            for (int mt = 0; mt < 2; mt++)
#pragma unroll
                for (int nt = 0; nt < 8; nt++) {
                    asm volatile(
                        "mma.sync.aligned.m16n8k8.row.col.f32.tf32.tf32.f32 "
                        "{%0,%1,%2,%3}, {%4,%5,%6,%7}, {%8,%9}, {%0,%1,%2,%3};"
                        : "+f"(acc[mt][nt][0]), "+f"(acc[mt][nt][1]),
                          "+f"(acc[mt][nt][2]), "+f"(acc[mt][nt][3])
                        : "r"(a[mt][0]), "r"(a[mt][1]),
                          "r"(a[mt][2]), "r"(a[mt][3]),
                          "r"(b[nt][0]), "r"(b[nt][1]));
                }
        }
        __syncthreads();
    }

    if (asrc == nullptr) {
#pragma unroll
        for (int mt = 0; mt < 2; mt++) {
            int row = bm + wm + mt * 16 + g;
#pragma unroll
            for (int nt = 0; nt < 8; nt++) {
                int col = wn + nt * 8 + 2 * tig;
                float bx = bias ? bias[col] : 0.f;
                float by = bias ? bias[col + 1] : 0.f;
                if (row < N_NODES)
                    *(float2*)(Cp + (size_t)row * D + col) =
                        make_float2(acc[mt][nt][0] + bx, acc[mt][nt][1] + by);
                if (row + 8 < N_NODES)
                    *(float2*)(Cp + (size_t)(row + 8) * D + col) =
                        make_float2(acc[mt][nt][2] + bx, acc[mt][nt][3] + by);
            }
        }
    } else {
        // xp epilogue: fp16 message store + fused logits (pre-scaled by LOG2E)
        const int head_base = (wn == 0) ? 0 : 2;
#pragma unroll
        for (int mt = 0; mt < 2; mt++) {
#pragma unroll
            for (int rh = 0; rh < 2; rh++) {
                int row = bm + wm + mt * 16 + rh * 8 + g;
                float ps0 = 0.f, ps1 = 0.f, pd0 = 0.f, pd1 = 0.f;
#pragma unroll
                for (int nt = 0; nt < 8; nt++) {
                    int col = wn + nt * 8 + 2 * tig;
                    int c = (nt & 3) * 8 + 2 * tig;
                    int hl = nt >> 2;
                    float v0 = acc[mt][nt][rh * 2 + 0];
                    float v1 = acc[mt][nt][rh * 2 + 1];
                    float s0 = __ldg(asrc + (head_base + hl) * 32 + c);
                    float s1 = __ldg(asrc + (head_base + hl) * 32 + c + 1);
                    float d0 = __ldg(adst + (head_base + hl) * 32 + c);
                    float d1 = __ldg(adst + (head_base + hl) * 32 + c + 1);
                    if (hl == 0) { ps0 += v0 * s0 + v1 * s1; pd0 += v0 * d0 + v1 * d1; }
                    else         { ps1 += v0 * s0 + v1 * s1; pd1 += v0 * d0 + v1 * d1; }
                    if (row < N_NODES)
                        *(__half2*)(g_xph + (size_t)row * D + col) =
                            __floats2half2_rn(v0, v1);
                }
#pragma unroll
                for (int off = 1; off < 4; off <<= 1) {
                    ps0 += __shfl_xor_sync(0xffffffffu, ps0, off);
                    ps1 += __shfl_xor_sync(0xffffffffu, ps1, off);
                    pd0 += __shfl_xor_sync(0xffffffffu, pd0, off);
                    pd1 += __shfl_xor_sync(0xffffffffu, pd1, off);
                }
                if (tig == 0 && row < N_NODES) {
                    g_als[row * 4 + head_base]     = ps0 * LOG2E;
                    g_als[row * 4 + head_base + 1] = ps1 * LOG2E;
                    g_ald[row * 4 + head_base]     = pd0 * LOG2E;
                    g_ald[row * 4 + head_base + 1] = pd1 * LOG2E;
                }
            }
        }
    }
}

// ---------------- scan1: 256-thr block scans 1024 nodes ----------------
__global__ void __launch_bounds__(256) k_scan1() {
    __shared__ int sm[256];
    int b = blockIdx.x;
    int t = threadIdx.x;
    int base = b * 1024 + t * 4;
    int v0 = 0, v1 = 0, v2 = 0, v3 = 0;
    if (base + 3 < N_NODES) {
        int4 d = *(int4*)&g_deg[base];
        v0 = d.x + 1; v1 = d.y + 1; v2 = d.z + 1; v3 = d.w + 1;
        *(int4*)&g_deg[base] = make_int4(0, 0, 0, 0);
    } else {
        if (base + 0 < N_NODES) { v0 = g_deg[base + 0] + 1; g_deg[base + 0] = 0; }
        if (base + 1 < N_NODES) { v1 = g_deg[base + 1] + 1; g_deg[base + 1] = 0; }
        if (base + 2 < N_NODES) { v2 = g_deg[base + 2] + 1; g_deg[base + 2] = 0; }
        if (base + 3 < N_NODES) { v3 = g_deg[base + 3] + 1; g_deg[base + 3] = 0; }
    }
    int s = v0 + v1 + v2 + v3;
    sm[t] = s;
    __syncthreads();
#pragma unroll
    for (int off = 1; off < 256; off <<= 1) {
        int x = (t >= off) ? sm[t - off] : 0;
        __syncthreads();
        sm[t] += x;
        __syncthreads();
    }
    int run = sm[t] - s;
    if (base + 0 < N_NODES) g_rowptr[base + 0] = run; run += v0;
    if (base + 1 < N_NODES) g_rowptr[base + 1] = run; run += v1;
    if (base + 2 < N_NODES) g_rowptr[base + 2] = run; run += v2;
    if (base + 3 < N_NODES) g_rowptr[base + 3] = run;
    if (t == 255) g_bsum[b] = sm[255];
}

// ---------------- scatter body (depends ONLY on scan1, not on any GEMM) -----
__device__ void scatter_body(int b, const int* __restrict__ ei) {
    __shared__ int sb[64];
    __shared__ int sb_ex[64];
    int t = threadIdx.x;
    if (t < 64) sb[t] = (t < NB) ? g_bsum[t] : 0;
    __syncthreads();
#pragma unroll
    for (int off = 1; off < 64; off <<= 1) {
        int x = (t < 64 && t >= off) ? sb[t - off] : 0;
        __syncthreads();
        if (t < 64) sb[t] += x;
        __syncthreads();
    }
    if (t < 64) sb_ex[t] = (t == 0) ? 0 : sb[t - 1];
    __syncthreads();
    if (b == 0 && t < 64) g_sbex[t] = sb_ex[t];   // publish for aggs

    int i = b * 256 + t;
    if (i < N_NODES) {
        int c = atomicAdd(&g_deg[i], 1);
        g_col[g_rowptr[i] + sb_ex[i >> 10] + c] = i;       // self loop
    } else if (i < N_NODES + N_EDGES) {
        int j = i - N_NODES;
        int s = ei[j], d = ei[N_EDGES + j];
        int c = atomicAdd(&g_deg[d], 1);
        g_col[g_rowptr[d] + sb_ex[d >> 10] + c] = s;
    }
}

// ---------------- fat kernels ----------------
__global__ void __launch_bounds__(256) k_fused0(
        const float* x, const float* __restrict__ w0,
        const float* __restrict__ b0, const int* __restrict__ ei) {
    if (blockIdx.x < GGRID) {
        gemm_body(x, 0, w0, b0, 0, nullptr, nullptr, blockIdx.x);
    } else {
        int i = (blockIdx.x - GGRID) * 256 + threadIdx.x;
        if (i < N_EDGES) atomicAdd(&g_deg[ei[N_EDGES + i]], 1);
    }
}

__global__ void __launch_bounds__(256) k_fused_g1sc(
        const float* __restrict__ W,
        const float* __restrict__ asrc, const float* __restrict__ adst,
        const int* __restrict__ ei) {
    if (blockIdx.x < GGRID) {
        gemm_body(nullptr, 0, W, nullptr, 0, asrc, adst, blockIdx.x);
    } else {
        scatter_body(blockIdx.x - GGRID, ei);
    }
}

__global__ void __launch_bounds__(256) k_gemm_tc(
        const float* Aext, int asel,
        const float* __restrict__ W,
        const float* __restrict__ bias,
        int csel,
        const float* __restrict__ asrc,
        const float* __restrict__ adst) {
    gemm_body(Aext, asel, W, bias, csel, asrc, adst, blockIdx.x);
}

// ---------------- softmax-aggregate: ONE warp per destination node ----------
// Issue-minimized: raw half2 msg loads (no per-edge cvt), p broadcast as
// half2, HMUL2/HFMA2 accumulation within each 4-edge group, fp32 flush per
// group. Logits pre-scaled by log2(e) -> EX2 only.
__global__ void __launch_bounds__(256) k_agg(
        int in_sel, float* out_ext, int out_sel,
        const float* __restrict__ bias, int relu_res) {
    int n = (blockIdx.x * blockDim.x + threadIdx.x) >> 5;
    if (n >= N_NODES) return;
    int lane = threadIdx.x & 31;
    const float* xin = (in_sel == 0) ? g_h : g_h2;
    float* outp = out_ext ? out_ext : (out_sel == 0 ? g_h : g_h2);
    int hh = lane >> 3;
    float ad = g_ald[n * 4 + hh];
    const __half* xb = g_xph + lane * 4;   // per-lane channel base

    int beg = __ldg(&g_rowptr[n]) + __ldg(&g_sbex[n >> 10]);
    int end = (n == N_NODES - 1) ? E_TOT
              : (__ldg(&g_rowptr[n + 1]) + __ldg(&g_sbex[(n + 1) >> 10]));

    float4 acc = make_float4(0.f, 0.f, 0.f, 0.f);
    float ssum = 0.f;

    int j = beg;
    for (; j + 4 <= end; j += 4) {
        int s0 = __ldg(&g_col[j]);
        int s1 = __ldg(&g_col[j + 1]);
        int s2 = __ldg(&g_col[j + 2]);
        int s3 = __ldg(&g_col[j + 3]);
        float a0 = __ldg(&g_als[(size_t)s0 * 4 + hh]);
        float a1 = __ldg(&g_als[(size_t)s1 * 4 + hh]);
        float a2 = __ldg(&g_als[(size_t)s2 * 4 + hh]);
        float a3 = __ldg(&g_als[(size_t)s3 * 4 + hh]);
        uint2 u0 = *(const uint2*)(xb + (size_t)s0 * D);
        uint2 u1 = *(const uint2*)(xb + (size_t)s1 * D);
        uint2 u2 = *(const uint2*)(xb + (size_t)s2 * D);
        uint2 u3 = *(const uint2*)(xb + (size_t)s3 * D);
        float e0 = a0 + ad; e0 = fmaxf(e0, 0.2f * e0);
        float e1 = a1 + ad; e1 = fmaxf(e1, 0.2f * e1);
        float e2 = a2 + ad; e2 = fmaxf(e2, 0.2f * e2);
        float e3 = a3 + ad; e3 = fmaxf(e3, 0.2f * e3);
        float p0 = exp2f(e0), p1 = exp2f(e1);
        float p2 = exp2f(e2), p3 = exp2f(e3);
        ssum += (p0 + p1) + (p2 + p3);
        // half2 accumulation within the 4-edge group
        __half2 ph0 = __float2half2_rn(p0);
        __half2 ph1 = __float2half2_rn(p1);
        __half2 ph2 = __float2half2_rn(p2);
        __half2 ph3 = __float2half2_rn(p3);
        __half2 alo = __hmul2(ph0, *(__half2*)&u0.x);
        __half2 ahi = __hmul2(ph0, *(__half2*)&u0.y);
        alo = __hfma2(ph1, *(__half2*)&u1.x, alo);
        ahi = __hfma2(ph1, *(__half2*)&u1.y, ahi);
        alo = __hfma2(ph2, *(__half2*)&u2.x, alo);
        ahi = __hfma2(ph2, *(__half2*)&u2.y, ahi);
        alo = __hfma2(ph3, *(__half2*)&u3.x, alo);
        ahi = __hfma2(ph3, *(__half2*)&u3.y, ahi);
        float2 flo = __half22float2(alo);
        float2 fhi = __half22float2(ahi);
        acc.x += flo.x; acc.y += flo.y;
        acc.z += fhi.x; acc.w += fhi.y;
    }
    // scalar fp32 tail (<4 edges)
    for (; j < end; j++) {
        int s0 = __ldg(&g_col[j]);
        float a0 = __ldg(&g_als[(size_t)s0 * 4 + hh]);
        uint2 u0 = *(const uint2*)(xb + (size_t)s0 * D);
        float e0 = a0 + ad; e0 = fmaxf(e0, 0.2f * e0);
        float p0 = exp2f(e0);
        ssum += p0;
        float2 f00 = __half22float2(*(__half2*)&u0.x);
        float2 f01 = __half22float2(*(__half2*)&u0.y);
        acc.x += p0 * f00.x; acc.y += p0 * f00.y;
        acc.z += p0 * f01.x; acc.w += p0 * f01.y;
    }

    float inv = 1.f / ssum;
    float4 bv = *(const float4*)(bias + lane * 4);
    float4 o;
    o.x = acc.x * inv + bv.x;
    o.y = acc.y * inv + bv.y;
    o.z = acc.z * inv + bv.z;
    o.w = acc.w * inv + bv.w;
    if (relu_res) {
        float4 r = *(const float4*)(xin + (size_t)n * D + lane * 4);
        o.x = fmaxf(o.x + r.x, 0.f);
        o.y = fmaxf(o.y + r.y, 0.f);
        o.z = fmaxf(o.z + r.z, 0.f);
        o.w = fmaxf(o.w + r.w, 0.f);
    }
    *(float4*)(outp + (size_t)n * D + lane * 4) = o;
    if (lane == 0) g_deg[n] = 0;       // reset cursor for next replay
}

// ---------------- launch (9 kernels) ----------------
extern "C" void kernel_launch(void* const* d_in, const int* in_sizes, int n_in,
                              void* d_out, int out_size) {
    const float* x   = (const float*)d_in[0];
    const int*   ei  = (const int*)  d_in[1];
    const float* w0  = (const float*)d_in[2];
    const float* b0  = (const float*)d_in[3];
    const float* w1  = (const float*)d_in[4];
    const float* as1 = (const float*)d_in[5];
    const float* ad1 = (const float*)d_in[6];
    const float* b1  = (const float*)d_in[7];
    const float* w2  = (const float*)d_in[8];
    const float* as2 = (const float*)d_in[9];
    const float* ad2 = (const float*)d_in[10];
    const float* b2  = (const float*)d_in[11];
    const float* w3  = (const float*)d_in[12];
    const float* as3 = (const float*)d_in[13];
    const float* ad3 = (const float*)d_in[14];
    const float* b3  = (const float*)d_in[15];
    float* out = (float*)d_out;

    int agrid = (N_NODES * 32) / 256;       // 6250 blocks, 1 warp per node

    // L0: gemm0 (x@w0+b0 -> g_h)  ∥  edge-count histogram
    k_fused0<<<GGRID + CNT_BLK, 256>>>(x, w0, b0, ei);
    // L1: scan1 (small; consumes count, zeroes deg)
    k_scan1<<<NB, 256>>>();
    // L2: gemm1 (g_h@w1 -> xph/als/ald)  ∥  scatter (independent of gemm1)
    k_fused_g1sc<<<GGRID + SCT_BLK, 256>>>(w1, as1, ad1, ei);
    // layer 1 aggregate: g_h residual -> g_h2
    k_agg<<<agrid, 256>>>(0, nullptr, 1, b1, 1);
    // layer 2
    k_gemm_tc<<<GGRID, 256>>>(nullptr, 1, w2, nullptr, 0, as2, ad2);
    k_agg<<<agrid, 256>>>(1, nullptr, 0, b2, 1);
    // layer 3
    k_gemm_tc<<<GGRID, 256>>>(nullptr, 0, w3, nullptr, 0, as3, ad3);
    k_agg<<<agrid, 256>>>(0, out, 0, b3, 0);
}